// round 1
// baseline (speedup 1.0000x reference)
#include <cuda_runtime.h>

#define N_USER 100000
#define N_ITEM 50000
#define NTOT   150000
#define EMB    64
#define FEAT   384
#define NNZ    2400000
#define EPS_F  1e-8f

// ---------------- device scratch (static, no allocations) ----------------
__device__ float g_ego[NTOT * EMB];      // 38.4 MB
__device__ float g_xA [NTOT * EMB];      // 38.4 MB
__device__ float g_xB [NTOT * EMB];      // 38.4 MB
__device__ float g_egonorm[NTOT];
__device__ int   g_counts[NTOT];
__device__ int   g_cursor[NTOT];
__device__ int   g_rowptr[NTOT + 1];
__device__ int   g_csrcol[NNZ];
__device__ float g_csrval[NNZ];
__device__ int   g_bsum[256];

// ---------------- CSR build ----------------
__global__ void k_zero()
{
    int i = blockIdx.x * blockDim.x + threadIdx.x;
    if (i < NTOT) { g_counts[i] = 0; g_cursor[i] = 0; }
}

__global__ void k_hist(const int* __restrict__ rows)
{
    int stride = gridDim.x * blockDim.x;
    for (int e = blockIdx.x * blockDim.x + threadIdx.x; e < NNZ; e += stride)
        atomicAdd(&g_counts[rows[e]], 1);
}

// block-wise exclusive scan (1024 elems per block)
__global__ void k_scan1()
{
    __shared__ int sh[1024];
    int tid = threadIdx.x;
    int gid = blockIdx.x * 1024 + tid;
    int v = (gid < NTOT) ? g_counts[gid] : 0;
    sh[tid] = v;
    __syncthreads();
    for (int o = 1; o < 1024; o <<= 1) {
        int t = (tid >= o) ? sh[tid - o] : 0;
        __syncthreads();
        if (tid >= o) sh[tid] += t;
        __syncthreads();
    }
    if (gid < NTOT) g_rowptr[gid] = sh[tid] - v;   // exclusive within block
    if (tid == 1023) g_bsum[blockIdx.x] = sh[1023];
}

__global__ void k_scan2(int nb)
{
    __shared__ int sh[256];
    int tid = threadIdx.x;
    int v = (tid < nb) ? g_bsum[tid] : 0;
    sh[tid] = v;
    __syncthreads();
    for (int o = 1; o < 256; o <<= 1) {
        int t = (tid >= o) ? sh[tid - o] : 0;
        __syncthreads();
        if (tid >= o) sh[tid] += t;
        __syncthreads();
    }
    g_bsum[tid] = sh[tid] - v;   // exclusive block offsets
}

__global__ void k_scan3()
{
    int gid = blockIdx.x * 1024 + threadIdx.x;
    if (gid < NTOT) g_rowptr[gid] += g_bsum[blockIdx.x];
    if (gid == 0) g_rowptr[NTOT] = NNZ;
}

__global__ void k_scatter(const int* __restrict__ rows,
                          const int* __restrict__ cols,
                          const float* __restrict__ vals)
{
    int stride = gridDim.x * blockDim.x;
    for (int e = blockIdx.x * blockDim.x + threadIdx.x; e < NNZ; e += stride) {
        int r = rows[e];
        int p = g_rowptr[r] + atomicAdd(&g_cursor[r], 1);
        g_csrcol[p] = cols[e];
        g_csrval[p] = vals[e];
    }
}

// ---------------- ego construction ----------------
__global__ void k_ego_user(const float* __restrict__ user,
                           const float* __restrict__ prompt,
                           float* __restrict__ out)
{
    __shared__ float ps[EMB];
    int tid = threadIdx.x;
    if (tid < EMB) {
        float s = 0.f;
#pragma unroll
        for (int p = 0; p < 8; p++) s += prompt[p * EMB + tid];
        ps[tid] = s;
    }
    __syncthreads();
    int stride = gridDim.x * blockDim.x;
    for (int i = blockIdx.x * blockDim.x + tid; i < N_USER * EMB; i += stride) {
        float v = user[i] + ps[i & 63];
        g_ego[i] = v;
        out[i]   = v;   // acc layer-0
    }
}

// tiled SGEMM: [N_ITEM,384] @ [384,64] + bias, tanh.  BM=128, BK=32, thread tile 8x4.
__global__ __launch_bounds__(256) void k_item(const float* __restrict__ fea,
                                              const float* __restrict__ w,
                                              const float* __restrict__ b,
                                              float* __restrict__ out)
{
    __shared__ float sf[128][33];
    __shared__ float sw[32][64];
    int tid = threadIdx.x;
    int row0 = blockIdx.x * 128;
    int ty = tid >> 4;      // 0..15, 8 rows each
    int tx = tid & 15;      // 0..15, 4 cols each

    float acc[8][4];
#pragma unroll
    for (int r = 0; r < 8; r++)
#pragma unroll
        for (int c = 0; c < 4; c++) acc[r][c] = 0.f;

    for (int k0 = 0; k0 < FEAT; k0 += 32) {
#pragma unroll
        for (int i = 0; i < 16; i++) {            // 128x32 fea tile
            int l = tid + i * 256;
            int r = l >> 5, kk = l & 31;
            int gr = row0 + r;
            sf[r][kk] = (gr < N_ITEM) ? fea[gr * FEAT + k0 + kk] : 0.f;
        }
#pragma unroll
        for (int i = 0; i < 8; i++) {             // 32x64 w tile
            int l = tid + i * 256;
            int kk = l >> 6, c = l & 63;
            sw[kk][c] = w[(k0 + kk) * EMB + c];
        }
        __syncthreads();
#pragma unroll
        for (int kk = 0; kk < 32; kk++) {
            float4 wv = *(const float4*)&sw[kk][tx * 4];
#pragma unroll
            for (int r = 0; r < 8; r++) {
                float f = sf[ty * 8 + r][kk];
                acc[r][0] += f * wv.x;
                acc[r][1] += f * wv.y;
                acc[r][2] += f * wv.z;
                acc[r][3] += f * wv.w;
            }
        }
        __syncthreads();
    }

#pragma unroll
    for (int r = 0; r < 8; r++) {
        int gr = row0 + ty * 8 + r;
        if (gr < N_ITEM) {
#pragma unroll
            for (int c = 0; c < 4; c++) {
                float v = tanhf(acc[r][c] + b[tx * 4 + c]);
                int idx = (N_USER + gr) * EMB + tx * 4 + c;
                g_ego[idx] = v;
                out[idx]   = v;   // acc layer-0
            }
        }
    }
}

__global__ void k_norm()
{
    int warp = (blockIdx.x * blockDim.x + threadIdx.x) >> 5;
    int lane = threadIdx.x & 31;
    if (warp >= NTOT) return;
    const float2* e = (const float2*)g_ego;
    float2 v = e[warp * 32 + lane];
    float s = v.x * v.x + v.y * v.y;
#pragma unroll
    for (int o = 16; o; o >>= 1) s += __shfl_xor_sync(0xffffffffu, s, o);
    if (lane == 0) g_egonorm[warp] = sqrtf(s);
}

// ---------------- fused SpMM + cosine-reweight + accumulate ----------------
__global__ __launch_bounds__(256) void k_layer(const float* __restrict__ xin,
                                               float* __restrict__ xout,
                                               float* __restrict__ acc)
{
    int warp = (blockIdx.x * blockDim.x + threadIdx.x) >> 5;
    int lane = threadIdx.x & 31;
    if (warp >= NTOT) return;

    int s = g_rowptr[warp];
    int e = g_rowptr[warp + 1];

    const float2* x2 = (const float2*)xin;
    float a0 = 0.f, a1 = 0.f;
#pragma unroll 4
    for (int p = s; p < e; p++) {
        int   c = __ldg(&g_csrcol[p]);
        float v = __ldg(&g_csrval[p]);
        float2 xv = __ldg(&x2[c * 32 + lane]);
        a0 += v * xv.x;
        a1 += v * xv.y;
    }

    const float2* eg = (const float2*)g_ego;
    float2 ev = eg[warp * 32 + lane];
    float dot = a0 * ev.x + a1 * ev.y;
    float nn  = a0 * a0 + a1 * a1;
#pragma unroll
    for (int o = 16; o; o >>= 1) {
        dot += __shfl_xor_sync(0xffffffffu, dot, o);
        nn  += __shfl_xor_sync(0xffffffffu, nn,  o);
    }
    float wgt = dot / fmaxf(sqrtf(nn) * g_egonorm[warp], EPS_F);

    float o0 = wgt * a0, o1 = wgt * a1;
    ((float2*)xout)[warp * 32 + lane] = make_float2(o0, o1);
    float2* ac = (float2*)acc;
    float2 av = ac[warp * 32 + lane];
    av.x += o0; av.y += o1;
    ac[warp * 32 + lane] = av;
}

// ---------------- launch ----------------
extern "C" void kernel_launch(void* const* d_in, const int* in_sizes, int n_in,
                              void* d_out, int out_size)
{
    const float* user   = (const float*)d_in[0];
    const float* item   = (const float*)d_in[1];
    const float* prompt = (const float*)d_in[2];
    const float* mw     = (const float*)d_in[3];
    const float* mb     = (const float*)d_in[4];
    const int*   rows   = (const int*)d_in[5];
    const int*   cols   = (const int*)d_in[6];
    const float* vals   = (const float*)d_in[7];
    float* out = (float*)d_out;

    void *pEgo, *pA, *pB;
    cudaGetSymbolAddress(&pEgo, g_ego);
    cudaGetSymbolAddress(&pA,   g_xA);
    cudaGetSymbolAddress(&pB,   g_xB);
    float* ego = (float*)pEgo;
    float* xA  = (float*)pA;
    float* xB  = (float*)pB;

    const int SCAN_BLOCKS = (NTOT + 1023) / 1024;   // 147

    // CSR build (identical for all 4 layers)
    k_zero   <<<(NTOT + 255) / 256, 256>>>();
    k_hist   <<<2048, 256>>>(rows);
    k_scan1  <<<SCAN_BLOCKS, 1024>>>();
    k_scan2  <<<1, 256>>>(SCAN_BLOCKS);
    k_scan3  <<<SCAN_BLOCKS, 1024>>>();
    k_scatter<<<2048, 256>>>(rows, cols, vals);

    // ego + acc init
    k_ego_user<<<4096, 256>>>(user, prompt, out);
    k_item    <<<(N_ITEM + 127) / 128, 256>>>(item, mw, mb, out);
    k_norm    <<<(NTOT * 32 + 255) / 256, 256>>>();

    // 4 propagation layers (warp-per-row, fused reweight + accumulate)
    const int LB = (NTOT * 32 + 255) / 256;   // 18750 blocks, 8 warps each
    k_layer<<<LB, 256>>>(ego, xA, out);
    k_layer<<<LB, 256>>>(xA,  xB, out);
    k_layer<<<LB, 256>>>(xB,  xA, out);
    k_layer<<<LB, 256>>>(xA,  xB, out);
}

// round 2
// speedup vs baseline: 1.1643x; 1.1643x over previous
#include <cuda_runtime.h>
#include <cuda_bf16.h>

#define N_USER 100000
#define N_ITEM 50000
#define NTOT   150000
#define EMB    64
#define FEAT   384
#define NNZ    2400000
#define EPS_F  1e-8f

// ---------------- device scratch (static, no allocations) ----------------
__device__ float          g_ego[NTOT * EMB];       // 38.4 MB fp32
__device__ __nv_bfloat162 g_ego16[NTOT * 32];      // 19.2 MB bf16
__device__ __nv_bfloat162 g_x1[NTOT * 32];         // layer outputs, bf16
__device__ __nv_bfloat162 g_x2[NTOT * 32];
__device__ __nv_bfloat162 g_x3[NTOT * 32];
__device__ float g_norm[NTOT];
__device__ int   g_counts[NTOT];
__device__ int   g_cursor[NTOT];
__device__ int   g_rowptr[NTOT + 1];
__device__ int2  g_edges[NNZ];                     // (col, val-bits) packed
__device__ int   g_bsum[256];

// ---------------- CSR build ----------------
__global__ void k_zero()
{
    int i = blockIdx.x * blockDim.x + threadIdx.x;
    if (i < NTOT) { g_counts[i] = 0; g_cursor[i] = 0; }
}

__global__ void k_hist(const int* __restrict__ rows)
{
    int stride = gridDim.x * blockDim.x;
    for (int e = blockIdx.x * blockDim.x + threadIdx.x; e < NNZ; e += stride)
        atomicAdd(&g_counts[rows[e]], 1);
}

__global__ void k_scan1()
{
    __shared__ int sh[1024];
    int tid = threadIdx.x;
    int gid = blockIdx.x * 1024 + tid;
    int v = (gid < NTOT) ? g_counts[gid] : 0;
    sh[tid] = v;
    __syncthreads();
    for (int o = 1; o < 1024; o <<= 1) {
        int t = (tid >= o) ? sh[tid - o] : 0;
        __syncthreads();
        if (tid >= o) sh[tid] += t;
        __syncthreads();
    }
    if (gid < NTOT) g_rowptr[gid] = sh[tid] - v;   // exclusive within block
    if (tid == 1023) g_bsum[blockIdx.x] = sh[1023];
}

__global__ void k_scan2(int nb)
{
    __shared__ int sh[256];
    int tid = threadIdx.x;
    int v = (tid < nb) ? g_bsum[tid] : 0;
    sh[tid] = v;
    __syncthreads();
    for (int o = 1; o < 256; o <<= 1) {
        int t = (tid >= o) ? sh[tid - o] : 0;
        __syncthreads();
        if (tid >= o) sh[tid] += t;
        __syncthreads();
    }
    g_bsum[tid] = sh[tid] - v;
}

__global__ void k_scan3()
{
    int gid = blockIdx.x * 1024 + threadIdx.x;
    if (gid < NTOT) g_rowptr[gid] += g_bsum[blockIdx.x];
    if (gid == 0) g_rowptr[NTOT] = NNZ;
}

__global__ void k_scatter(const int* __restrict__ rows,
                          const int* __restrict__ cols,
                          const float* __restrict__ vals)
{
    int stride = gridDim.x * blockDim.x;
    for (int e = blockIdx.x * blockDim.x + threadIdx.x; e < NNZ; e += stride) {
        int r = rows[e];
        int p = g_rowptr[r] + atomicAdd(&g_cursor[r], 1);
        g_edges[p] = make_int2(cols[e], __float_as_int(vals[e]));
    }
}

// ---------------- ego construction ----------------
__global__ void k_ego_user(const float* __restrict__ user,
                           const float* __restrict__ prompt)
{
    __shared__ float ps[EMB];
    int tid = threadIdx.x;
    if (tid < EMB) {
        float s = 0.f;
#pragma unroll
        for (int p = 0; p < 8; p++) s += prompt[p * EMB + tid];
        ps[tid] = s;
    }
    __syncthreads();
    int stride = gridDim.x * blockDim.x;
    for (int i = blockIdx.x * blockDim.x + tid; i < N_USER * EMB; i += stride)
        g_ego[i] = user[i] + ps[i & 63];
}

// tiled SGEMM: [N_ITEM,384] @ [384,64] + bias, tanh.  BM=128, BK=32, thread tile 8x4.
__global__ __launch_bounds__(256) void k_item(const float* __restrict__ fea,
                                              const float* __restrict__ w,
                                              const float* __restrict__ b)
{
    __shared__ float sf[128][33];
    __shared__ float sw[32][64];
    int tid = threadIdx.x;
    int row0 = blockIdx.x * 128;
    int ty = tid >> 4;
    int tx = tid & 15;

    float acc[8][4];
#pragma unroll
    for (int r = 0; r < 8; r++)
#pragma unroll
        for (int c = 0; c < 4; c++) acc[r][c] = 0.f;

    for (int k0 = 0; k0 < FEAT; k0 += 32) {
#pragma unroll
        for (int i = 0; i < 16; i++) {
            int l = tid + i * 256;
            int r = l >> 5, kk = l & 31;
            int gr = row0 + r;
            sf[r][kk] = (gr < N_ITEM) ? fea[gr * FEAT + k0 + kk] : 0.f;
        }
#pragma unroll
        for (int i = 0; i < 8; i++) {
            int l = tid + i * 256;
            int kk = l >> 6, c = l & 63;
            sw[kk][c] = w[(k0 + kk) * EMB + c];
        }
        __syncthreads();
#pragma unroll
        for (int kk = 0; kk < 32; kk++) {
            float4 wv = *(const float4*)&sw[kk][tx * 4];
#pragma unroll
            for (int r = 0; r < 8; r++) {
                float f = sf[ty * 8 + r][kk];
                acc[r][0] += f * wv.x;
                acc[r][1] += f * wv.y;
                acc[r][2] += f * wv.z;
                acc[r][3] += f * wv.w;
            }
        }
        __syncthreads();
    }

#pragma unroll
    for (int r = 0; r < 8; r++) {
        int gr = row0 + ty * 8 + r;
        if (gr < N_ITEM) {
#pragma unroll
            for (int c = 0; c < 4; c++) {
                float v = tanhf(acc[r][c] + b[tx * 4 + c]);
                g_ego[(N_USER + gr) * EMB + tx * 4 + c] = v;
            }
        }
    }
}

// norms + bf16 conversion of ego, one pass
__global__ void k_norm_cvt()
{
    int warp = (blockIdx.x * blockDim.x + threadIdx.x) >> 5;
    int lane = threadIdx.x & 31;
    if (warp >= NTOT) return;
    float2 v = ((const float2*)g_ego)[warp * 32 + lane];
    g_ego16[warp * 32 + lane] = __floats2bfloat162_rn(v.x, v.y);
    float s = v.x * v.x + v.y * v.y;
#pragma unroll
    for (int o = 16; o; o >>= 1) s += __shfl_xor_sync(0xffffffffu, s, o);
    if (lane == 0) g_norm[warp] = sqrtf(s);
}

// ---------------- fused SpMM + cosine-reweight (bf16 in/out) ----------------
__global__ __launch_bounds__(256) void k_layerA(const __nv_bfloat162* __restrict__ xin,
                                                __nv_bfloat162* __restrict__ xout)
{
    int warp = (blockIdx.x * blockDim.x + threadIdx.x) >> 5;
    int lane = threadIdx.x & 31;
    if (warp >= NTOT) return;

    int s = g_rowptr[warp];
    int e = g_rowptr[warp + 1];

    float a0 = 0.f, a1 = 0.f;
#pragma unroll 4
    for (int p = s; p < e; p++) {
        int2 ed = __ldg(&g_edges[p]);
        float v = __int_as_float(ed.y);
        float2 f = __bfloat1622float2(__ldg(&xin[ed.x * 32 + lane]));
        a0 += v * f.x;
        a1 += v * f.y;
    }

    float2 ev = __bfloat1622float2(g_ego16[warp * 32 + lane]);
    float dot = a0 * ev.x + a1 * ev.y;
    float nn  = a0 * a0 + a1 * a1;
#pragma unroll
    for (int o = 16; o; o >>= 1) {
        dot += __shfl_xor_sync(0xffffffffu, dot, o);
        nn  += __shfl_xor_sync(0xffffffffu, nn,  o);
    }
    float wgt = dot / fmaxf(sqrtf(nn) * g_norm[warp], EPS_F);

    xout[warp * 32 + lane] = __floats2bfloat162_rn(wgt * a0, wgt * a1);
}

// final layer: SpMM + reweight + fused total sum  out = ego + x1 + x2 + x3 + x4
__global__ __launch_bounds__(256) void k_layerB(float* __restrict__ out)
{
    int warp = (blockIdx.x * blockDim.x + threadIdx.x) >> 5;
    int lane = threadIdx.x & 31;
    if (warp >= NTOT) return;

    int s = g_rowptr[warp];
    int e = g_rowptr[warp + 1];

    float a0 = 0.f, a1 = 0.f;
#pragma unroll 4
    for (int p = s; p < e; p++) {
        int2 ed = __ldg(&g_edges[p]);
        float v = __int_as_float(ed.y);
        float2 f = __bfloat1622float2(__ldg(&g_x3[ed.x * 32 + lane]));
        a0 += v * f.x;
        a1 += v * f.y;
    }

    int idx = warp * 32 + lane;
    float2 ev = ((const float2*)g_ego)[idx];     // fp32 ego, exact
    float dot = a0 * ev.x + a1 * ev.y;
    float nn  = a0 * a0 + a1 * a1;
#pragma unroll
    for (int o = 16; o; o >>= 1) {
        dot += __shfl_xor_sync(0xffffffffu, dot, o);
        nn  += __shfl_xor_sync(0xffffffffu, nn,  o);
    }
    float wgt = dot / fmaxf(sqrtf(nn) * g_norm[warp], EPS_F);

    float2 v1 = __bfloat1622float2(g_x1[idx]);
    float2 v2 = __bfloat1622float2(g_x2[idx]);
    float2 v3 = __bfloat1622float2(g_x3[idx]);
    float2 r;
    r.x = ev.x + v1.x + v2.x + v3.x + wgt * a0;
    r.y = ev.y + v1.y + v2.y + v3.y + wgt * a1;
    ((float2*)out)[idx] = r;
}

// ---------------- launch ----------------
extern "C" void kernel_launch(void* const* d_in, const int* in_sizes, int n_in,
                              void* d_out, int out_size)
{
    const float* user   = (const float*)d_in[0];
    const float* item   = (const float*)d_in[1];
    const float* prompt = (const float*)d_in[2];
    const float* mw     = (const float*)d_in[3];
    const float* mb     = (const float*)d_in[4];
    const int*   rows   = (const int*)d_in[5];
    const int*   cols   = (const int*)d_in[6];
    const float* vals   = (const float*)d_in[7];
    float* out = (float*)d_out;

    void *p16, *p1, *p2, *p3;
    cudaGetSymbolAddress(&p16, g_ego16);
    cudaGetSymbolAddress(&p1,  g_x1);
    cudaGetSymbolAddress(&p2,  g_x2);
    cudaGetSymbolAddress(&p3,  g_x3);
    __nv_bfloat162* ego16 = (__nv_bfloat162*)p16;
    __nv_bfloat162* x1    = (__nv_bfloat162*)p1;
    __nv_bfloat162* x2    = (__nv_bfloat162*)p2;
    __nv_bfloat162* x3    = (__nv_bfloat162*)p3;

    const int SCAN_BLOCKS = (NTOT + 1023) / 1024;   // 147

    // CSR build
    k_zero   <<<(NTOT + 255) / 256, 256>>>();
    k_hist   <<<2048, 256>>>(rows);
    k_scan1  <<<SCAN_BLOCKS, 1024>>>();
    k_scan2  <<<1, 256>>>(SCAN_BLOCKS);
    k_scan3  <<<SCAN_BLOCKS, 1024>>>();
    k_scatter<<<2048, 256>>>(rows, cols, vals);

    // ego + norms + bf16 mirror
    k_ego_user<<<4096, 256>>>(user, prompt);
    k_item    <<<(N_ITEM + 127) / 128, 256>>>(item, mw, mb);
    k_norm_cvt<<<(NTOT * 32 + 255) / 256, 256>>>();

    // 4 propagation layers
    const int LB = (NTOT * 32 + 255) / 256;   // 18750 blocks
    k_layerA<<<LB, 256>>>(ego16, x1);
    k_layerA<<<LB, 256>>>(x1,    x2);
    k_layerA<<<LB, 256>>>(x2,    x3);
    k_layerB<<<LB, 256>>>(out);
}